// round 5
// baseline (speedup 1.0000x reference)
#include <cuda_runtime.h>
#include <stdint.h>

#define B_  2
#define M_  2048
#define N_  2048
#define D_  1024
#define NH_ 16
#define DH_ 64

// Scratch (device globals: no allocation allowed)
__device__ float g_Q[(size_t)B_ * M_ * D_];
__device__ float g_K[(size_t)B_ * N_ * D_];
__device__ float g_V[(size_t)B_ * N_ * D_];
__device__ float g_C[(size_t)B_ * M_ * D_];
__device__ unsigned char g_mask[B_ * N_];

// ---------------------------------------------------------------------------
// helpers
// ---------------------------------------------------------------------------
__device__ __forceinline__ unsigned f2tf(float x) {
    unsigned u; asm("cvt.rna.tf32.f32 %0, %1;" : "=r"(u) : "f"(x)); return u;
}
__device__ __forceinline__ unsigned f2tf_s(float x) {   // from smem float
    unsigned u; asm("cvt.rna.tf32.f32 %0, %1;" : "=r"(u) : "f"(x)); return u;
}
__device__ __forceinline__ float ex2(float x) {
    float y; asm("ex2.approx.f32 %0, %1;" : "=f"(y) : "f"(x)); return y;
}
__device__ __forceinline__ void mma8(float* c, unsigned a0, unsigned a1, unsigned a2, unsigned a3,
                                     unsigned b0, unsigned b1) {
    asm volatile(
        "mma.sync.aligned.m16n8k8.row.col.f32.tf32.tf32.f32 "
        "{%0,%1,%2,%3},{%4,%5,%6,%7},{%8,%9},{%0,%1,%2,%3};\n"
        : "+f"(c[0]), "+f"(c[1]), "+f"(c[2]), "+f"(c[3])
        : "r"(a0), "r"(a1), "r"(a2), "r"(a3), "r"(b0), "r"(b1));
}
__device__ __forceinline__ void cpasync16(void* dst, const void* src) {
    unsigned d = (unsigned)__cvta_generic_to_shared(dst);
    asm volatile("cp.async.cg.shared.global [%0], [%1], 16;\n" :: "r"(d), "l"(src));
}
#define CP_COMMIT() asm volatile("cp.async.commit_group;\n" ::: "memory")
#define CP_WAIT0()  asm volatile("cp.async.wait_group 0;\n" ::: "memory")
#define CP_WAIT1()  asm volatile("cp.async.wait_group 1;\n" ::: "memory")
#define CP_WAIT2()  asm volatile("cp.async.wait_group 2;\n" ::: "memory")

// ---------------------------------------------------------------------------
// Mask dtype sniffer + expander (bool may arrive as u8 / i32 / f32)
// ---------------------------------------------------------------------------
__global__ void mask_expand_kernel(const unsigned char* __restrict__ raw) {
    __shared__ int s_not_int, s_not_float;
    if (threadIdx.x == 0) { s_not_int = 0; s_not_float = 0; }
    __syncthreads();
    const unsigned int* w = (const unsigned int*)raw;
    for (int i = threadIdx.x; i < 1024; i += blockDim.x) {
        unsigned int x = w[i];
        if (x != 0u && x != 1u)          atomicOr(&s_not_int, 1);
        if (x != 0u && x != 0x3F800000u) atomicOr(&s_not_float, 1);
    }
    __syncthreads();
    int mode = (!s_not_int) ? 0 : ((!s_not_float) ? 1 : 2);
    if (mode == 2) {
        for (int i = threadIdx.x; i < B_ * N_; i += blockDim.x)
            g_mask[i] = raw[i] ? 1 : 0;
    } else {
        for (int i = threadIdx.x; i < B_ * N_; i += blockDim.x)
            g_mask[i] = w[i] ? 1 : 0;
    }
}

// ---------------------------------------------------------------------------
// TF32 GEMM: C[.,1024] = A[.,1024] @ B[1024,1024] row-major fp32.
// 128x128 block tile, BK=16, cp.async 3-stage pipeline, 256 threads,
// __launch_bounds__(256,2) pins regs <=127 for 2 blocks/SM.
// ---------------------------------------------------------------------------
#define GA_STR 20                       // 16 + 4 pad (words)
#define GB_STR 136                      // 128 + 8 pad
#define GA_WORDS (128 * GA_STR)         // 2560
#define GB_WORDS (16 * GB_STR)          // 2176

__device__ __forceinline__ void gemm_stage_load(
    const float* __restrict__ A, const float* __restrict__ Bm,
    int rowBase, int colBase, int k0, float* As, float* Bs, int tid)
{
#pragma unroll
    for (int i = 0; i < 2; ++i) {
        int f = tid + i * 256;
        int r = f >> 2, c = (f & 3) * 4;           // 128 rows x 16 cols
        cpasync16(As + r * GA_STR + c, A + (size_t)(rowBase + r) * D_ + k0 + c);
    }
#pragma unroll
    for (int i = 0; i < 2; ++i) {
        int f = tid + i * 256;
        int r = f >> 5, c = (f & 31) * 4;          // 16 rows x 128 cols
        cpasync16(Bs + r * GB_STR + c, Bm + (size_t)(k0 + r) * D_ + colBase + c);
    }
}

__device__ __forceinline__ void gemm_body(
    const float* __restrict__ A, const float* __restrict__ Bm, float* __restrict__ C)
{
    __shared__ float As[3][GA_WORDS];
    __shared__ float Bs[3][GB_WORDS];

    const int tid  = threadIdx.x;
    const int warp = tid >> 5, lane = tid & 31;
    const int g = lane >> 2, t = lane & 3;
    const int wm = (warp >> 2) * 64;
    const int wn = (warp & 3) * 32;
    const int rowBase = blockIdx.y * 128;
    const int colBase = blockIdx.x * 128;

    float acc[4][4][4];
#pragma unroll
    for (int i = 0; i < 4; ++i)
#pragma unroll
        for (int j = 0; j < 4; ++j)
#pragma unroll
            for (int k = 0; k < 4; ++k) acc[i][j][k] = 0.f;

    gemm_stage_load(A, Bm, rowBase, colBase, 0,  As[0], Bs[0], tid);
    CP_COMMIT();
    gemm_stage_load(A, Bm, rowBase, colBase, 16, As[1], Bs[1], tid);
    CP_COMMIT();

    const int NIT = D_ / 16;   // 64
    for (int it = 0; it < NIT; ++it) {
        const int cur = it % 3;
        const int pf = it + 2;
        if (pf < NIT)
            gemm_stage_load(A, Bm, rowBase, colBase, pf * 16,
                            As[pf % 3], Bs[pf % 3], tid);
        CP_COMMIT();           // uniform group counting (empty group if no load)
        CP_WAIT2();            // tile `it` (group it) guaranteed complete
        __syncthreads();

        const float* Ac = As[cur];
        const float* Bc = Bs[cur];
#pragma unroll
        for (int kk = 0; kk < 2; ++kk) {
            const int kb = kk * 8;
            unsigned a[4][4], bf[4][2];
#pragma unroll
            for (int mt = 0; mt < 4; ++mt) {
                int mr = wm + mt * 16;
                a[mt][0] = f2tf(Ac[(mr + g) * GA_STR + kb + t]);
                a[mt][1] = f2tf(Ac[(mr + g + 8) * GA_STR + kb + t]);
                a[mt][2] = f2tf(Ac[(mr + g) * GA_STR + kb + t + 4]);
                a[mt][3] = f2tf(Ac[(mr + g + 8) * GA_STR + kb + t + 4]);
            }
#pragma unroll
            for (int nt = 0; nt < 4; ++nt) {
                int nc = wn + nt * 8 + g;
                bf[nt][0] = f2tf(Bc[(kb + t) * GB_STR + nc]);
                bf[nt][1] = f2tf(Bc[(kb + t + 4) * GB_STR + nc]);
            }
#pragma unroll
            for (int mt = 0; mt < 4; ++mt)
#pragma unroll
                for (int nt = 0; nt < 4; ++nt)
                    mma8(acc[mt][nt], a[mt][0], a[mt][1], a[mt][2], a[mt][3],
                         bf[nt][0], bf[nt][1]);
        }
        __syncthreads();       // all reads done before stage reuse
    }

#pragma unroll
    for (int mt = 0; mt < 4; ++mt) {
        int r0 = rowBase + wm + mt * 16 + g;
#pragma unroll
        for (int nt = 0; nt < 4; ++nt) {
            int c0 = colBase + wn + nt * 8 + 2 * t;
            *(float2*)(C + (size_t)r0 * D_ + c0) =
                make_float2(acc[mt][nt][0], acc[mt][nt][1]);
            *(float2*)(C + (size_t)(r0 + 8) * D_ + c0) =
                make_float2(acc[mt][nt][2], acc[mt][nt][3]);
        }
    }
}

__global__ __launch_bounds__(256, 2) void gemm_qkv(
    const float* __restrict__ q, const float* __restrict__ kv,
    const float* __restrict__ WQ, const float* __restrict__ WK,
    const float* __restrict__ WV)
{
    const float *A, *Bm; float* C;
    if (blockIdx.z == 0)      { A = q;  Bm = WQ; C = g_Q; }
    else if (blockIdx.z == 1) { A = kv; Bm = WK; C = g_K; }
    else                      { A = kv; Bm = WV; C = g_V; }
    gemm_body(A, Bm, C);
}

__global__ __launch_bounds__(256, 2) void gemm_single(
    const float* __restrict__ A, const float* __restrict__ Bm, float* __restrict__ C)
{
    gemm_body(A, Bm, C);
}

// ---------------------------------------------------------------------------
// TF32 flash attention with cp.async double-buffered K/V (raw fp32 staged,
// tf32 convert at fragment load). Block = 64 query rows of one (b,h),
// 4 warps x 16 rows. Grid: (M/64, NH, B). Dynamic smem ~107KB -> 2 blk/SM.
// ---------------------------------------------------------------------------
#define AQ_STR 68
#define AK_STR 68
#define AV_STR 72
#define AP_STR 68
#define AQ_OFF 0
#define AK_OFF (64 * AQ_STR)                    // 4352
#define AK_STAGE (64 * AK_STR)                  // 4352
#define AV_OFF (AK_OFF + 2 * AK_STAGE)          // 13056
#define AV_STAGE (64 * AV_STR)                  // 4608
#define AP_OFF (AV_OFF + 2 * AV_STAGE)          // 22272
#define AMB_OFF (AP_OFF + 64 * AP_STR)          // 26624
#define ATT_WORDS (AMB_OFF + 64)                // 26688 -> 106752 B

#define M_INIT (-1.0e4f)
#define MASK_BIAS (-1.0e9f)

__global__ __launch_bounds__(128) void attn_tc(
    const float* __restrict__ Q, const float* __restrict__ K,
    const float* __restrict__ V, float* __restrict__ Cout)
{
    extern __shared__ float smemf[];
    unsigned* Qs = (unsigned*)(smemf + AQ_OFF);     // tf32
    float*    Kr = smemf + AK_OFF;                  // raw fp32, 2 stages
    float*    Vr = smemf + AV_OFF;                  // raw fp32, 2 stages
    unsigned* Ps = (unsigned*)(smemf + AP_OFF);     // tf32
    float* mbias = smemf + AMB_OFF;

    const int mtile = blockIdx.x, h = blockIdx.y, b = blockIdx.z;
    const int tid = threadIdx.x;
    const int warp = tid >> 5, lane = tid & 31;
    const int g = lane >> 2, t = lane & 3;
    const int mb = warp * 16;
    const int lr = tid >> 1, lch = (tid & 1) * 32;  // loader row / col-half

    const float* Kbase = K + ((size_t)b * N_) * D_ + h * DH_;
    const float* Vbase = V + ((size_t)b * N_) * D_ + h * DH_;

    // Preload tile 0 K/V (async) — overlaps with Q load below
    {
        const float* ks = Kbase + (size_t)lr * D_ + lch;
        const float* vs = Vbase + (size_t)lr * D_ + lch;
        float* kd = Kr + lr * AK_STR + lch;
        float* vd = Vr + lr * AV_STR + lch;
#pragma unroll
        for (int i = 0; i < 8; ++i) cpasync16(kd + 4 * i, ks + 4 * i);
#pragma unroll
        for (int i = 0; i < 8; ++i) cpasync16(vd + 4 * i, vs + 4 * i);
    }
    CP_COMMIT();

    // Q tile (scale & log2e folded), sync load
    {
        const float SC = 0.125f * 1.44269504f;
        const float4* qrow = (const float4*)(Q + ((size_t)(b * M_ + mtile * 64 + lr)) * D_ + h * DH_ + lch);
#pragma unroll
        for (int i = 0; i < 8; ++i) {
            float4 v = qrow[i];
            Qs[lr * AQ_STR + lch + 4 * i + 0] = f2tf(v.x * SC);
            Qs[lr * AQ_STR + lch + 4 * i + 1] = f2tf(v.y * SC);
            Qs[lr * AQ_STR + lch + 4 * i + 2] = f2tf(v.z * SC);
            Qs[lr * AQ_STR + lch + 4 * i + 3] = f2tf(v.w * SC);
        }
    }

    float m0 = M_INIT, m1 = M_INIT, l0 = 0.f, l1 = 0.f;
    float o[8][4];
#pragma unroll
    for (int i = 0; i < 8; ++i)
#pragma unroll
        for (int j = 0; j < 4; ++j) o[i][j] = 0.f;

    const int NT = N_ / 64;  // 32
    for (int kt = 0; kt < NT; ++kt) {
        const int cur = kt & 1;
        // prefetch next tile into other stage
        if (kt + 1 < NT) {
            const int nrow = (kt + 1) * 64 + lr;
            const float* ks = Kbase + (size_t)nrow * D_ + lch;
            const float* vs = Vbase + (size_t)nrow * D_ + lch;
            float* kd = Kr + (cur ^ 1) * AK_STAGE + lr * AK_STR + lch;
            float* vd = Vr + (cur ^ 1) * AV_STAGE + lr * AV_STR + lch;
#pragma unroll
            for (int i = 0; i < 8; ++i) cpasync16(kd + 4 * i, ks + 4 * i);
#pragma unroll
            for (int i = 0; i < 8; ++i) cpasync16(vd + 4 * i, vs + 4 * i);
            CP_COMMIT();
        }
        // mask bias for this tile
        if (tid < 64)
            mbias[tid] = g_mask[b * N_ + kt * 64 + tid] ? MASK_BIAS : 0.f;
        if (kt + 1 < NT) CP_WAIT1(); else CP_WAIT0();
        __syncthreads();   // tile data + mbias visible

        const float* Kc = Kr + cur * AK_STAGE;
        const float* Vc = Vr + cur * AV_STAGE;

        // S = Q K^T  (per warp m16 x n64, k=64)
        float s[8][4];
#pragma unroll
        for (int i = 0; i < 8; ++i)
#pragma unroll
            for (int j = 0; j < 4; ++j) s[i][j] = 0.f;

#pragma unroll
        for (int kk = 0; kk < 8; ++kk) {
            const int kb = kk * 8;
            unsigned a0 = Qs[(mb + g) * AQ_STR + kb + t];
            unsigned a1 = Qs[(mb + g + 8) * AQ_STR + kb + t];
            unsigned a2 = Qs[(mb + g) * AQ_STR + kb + t + 4];
            unsigned a3 = Qs[(mb + g + 8) * AQ_STR + kb + t + 4];
#pragma unroll
            for (int nt = 0; nt < 8; ++nt) {
                unsigned b0 = f2tf_s(Kc[(nt * 8 + g) * AK_STR + kb + t]);
                unsigned b1 = f2tf_s(Kc[(nt * 8 + g) * AK_STR + kb + t + 4]);
                mma8(s[nt], a0, a1, a2, a3, b0, b1);
            }
        }

        // online softmax (base-2)
        float mx0 = -3.0e38f, mx1 = -3.0e38f;
#pragma unroll
        for (int nt = 0; nt < 8; ++nt) {
            float b0 = mbias[nt * 8 + 2 * t];
            float b1 = mbias[nt * 8 + 2 * t + 1];
            s[nt][0] += b0; s[nt][1] += b1;
            s[nt][2] += b0; s[nt][3] += b1;
            mx0 = fmaxf(mx0, fmaxf(s[nt][0], s[nt][1]));
            mx1 = fmaxf(mx1, fmaxf(s[nt][2], s[nt][3]));
        }
        mx0 = fmaxf(mx0, __shfl_xor_sync(0xFFFFFFFFu, mx0, 1));
        mx0 = fmaxf(mx0, __shfl_xor_sync(0xFFFFFFFFu, mx0, 2));
        mx1 = fmaxf(mx1, __shfl_xor_sync(0xFFFFFFFFu, mx1, 1));
        mx1 = fmaxf(mx1, __shfl_xor_sync(0xFFFFFFFFu, mx1, 2));
        float nm0 = fmaxf(m0, mx0), nm1 = fmaxf(m1, mx1);
        float cr0 = ex2(m0 - nm0), cr1 = ex2(m1 - nm1);
        m0 = nm0; m1 = nm1;

        float rs0 = 0.f, rs1 = 0.f;
#pragma unroll
        for (int nt = 0; nt < 8; ++nt) {
            s[nt][0] = ex2(s[nt][0] - nm0);
            s[nt][1] = ex2(s[nt][1] - nm0);
            s[nt][2] = ex2(s[nt][2] - nm1);
            s[nt][3] = ex2(s[nt][3] - nm1);
            rs0 += s[nt][0] + s[nt][1];
            rs1 += s[nt][2] + s[nt][3];
        }
        l0 = l0 * cr0 + rs0;
        l1 = l1 * cr1 + rs1;

#pragma unroll
        for (int nt = 0; nt < 8; ++nt) {
            o[nt][0] *= cr0; o[nt][1] *= cr0;
            o[nt][2] *= cr1; o[nt][3] *= cr1;
            Ps[(mb + g) * AP_STR + nt * 8 + 2 * t]         = f2tf(s[nt][0]);
            Ps[(mb + g) * AP_STR + nt * 8 + 2 * t + 1]     = f2tf(s[nt][1]);
            Ps[(mb + g + 8) * AP_STR + nt * 8 + 2 * t]     = f2tf(s[nt][2]);
            Ps[(mb + g + 8) * AP_STR + nt * 8 + 2 * t + 1] = f2tf(s[nt][3]);
        }
        __syncwarp();

        // O += P V  (per warp m16 x n64(dh), k=64(keys))
#pragma unroll
        for (int kk = 0; kk < 8; ++kk) {
            const int kb = kk * 8;
            unsigned a0 = Ps[(mb + g) * AP_STR + kb + t];
            unsigned a1 = Ps[(mb + g + 8) * AP_STR + kb + t];
            unsigned a2 = Ps[(mb + g) * AP_STR + kb + t + 4];
            unsigned a3 = Ps[(mb + g + 8) * AP_STR + kb + t + 4];
#pragma unroll
            for (int nt = 0; nt < 8; ++nt) {
                unsigned b0 = f2tf_s(Vc[(kb + t) * AV_STR + nt * 8 + g]);
                unsigned b1 = f2tf_s(Vc[(kb + t + 4) * AV_STR + nt * 8 + g]);
                mma8(o[nt], a0, a1, a2, a3, b0, b1);
            }
        }
        __syncthreads();   // all reads of this stage done before its reuse
    }

    l0 += __shfl_xor_sync(0xFFFFFFFFu, l0, 1);
    l0 += __shfl_xor_sync(0xFFFFFFFFu, l0, 2);
    l1 += __shfl_xor_sync(0xFFFFFFFFu, l1, 1);
    l1 += __shfl_xor_sync(0xFFFFFFFFu, l1, 2);
    float inv0 = 1.f / l0, inv1 = 1.f / l1;

    const int gr0 = mtile * 64 + mb + g;
    const int gr1 = gr0 + 8;
#pragma unroll
    for (int nt = 0; nt < 8; ++nt) {
        int col = h * DH_ + nt * 8 + 2 * t;
        *(float2*)(Cout + ((size_t)(b * M_ + gr0)) * D_ + col) =
            make_float2(o[nt][0] * inv0, o[nt][1] * inv0);
        *(float2*)(Cout + ((size_t)(b * M_ + gr1)) * D_ + col) =
            make_float2(o[nt][2] * inv1, o[nt][3] * inv1);
    }
}

// ---------------------------------------------------------------------------
// Launch. Inputs: query, key_value, key_padding_mask, W_Q, W_K, W_V, W_O
// ---------------------------------------------------------------------------
extern "C" void kernel_launch(void* const* d_in, const int* in_sizes, int n_in,
                              void* d_out, int out_size)
{
    const float* query = (const float*)d_in[0];
    const float* keyv  = (const float*)d_in[1];
    const unsigned char* mask_raw = (const unsigned char*)d_in[2];
    const float* W_Q = (const float*)d_in[3];
    const float* W_K = (const float*)d_in[4];
    const float* W_V = (const float*)d_in[5];
    const float* W_O = (const float*)d_in[6];
    float* out = (float*)d_out;

    float *gQ, *gK, *gV, *gC;
    cudaGetSymbolAddress((void**)&gQ, g_Q);
    cudaGetSymbolAddress((void**)&gK, g_K);
    cudaGetSymbolAddress((void**)&gV, g_V);
    cudaGetSymbolAddress((void**)&gC, g_C);

    cudaFuncSetAttribute(attn_tc, cudaFuncAttributeMaxDynamicSharedMemorySize,
                         ATT_WORDS * 4);

    mask_expand_kernel<<<1, 1024>>>(mask_raw);

    dim3 gqkv(D_ / 128, (B_ * M_) / 128, 3);
    gemm_qkv<<<gqkv, 256>>>(query, keyv, W_Q, W_K, W_V);

    dim3 gattn(M_ / 64, NH_, B_);
    attn_tc<<<gattn, 128, ATT_WORDS * 4>>>(gQ, gK, gV, gC);

    dim3 gout(D_ / 128, (B_ * M_) / 128);
    gemm_single<<<gout, 256>>>(gC, W_O, out);
}

// round 6
// speedup vs baseline: 1.5790x; 1.5790x over previous
#include <cuda_runtime.h>
#include <stdint.h>

#define B_  2
#define M_  2048
#define N_  2048
#define D_  1024
#define NH_ 16
#define DH_ 64

// Scratch (device globals: no allocation allowed)
// g_Q holds tf32-rounded (Q*scale*log2e) bits; g_K/g_V hold tf32-rounded bits.
__device__ float g_Q[(size_t)B_ * M_ * D_];
__device__ float g_K[(size_t)B_ * N_ * D_];
__device__ float g_V[(size_t)B_ * N_ * D_];
__device__ float g_C[(size_t)B_ * M_ * D_];
__device__ unsigned char g_mask[B_ * N_];

// ---------------------------------------------------------------------------
// helpers
// ---------------------------------------------------------------------------
__device__ __forceinline__ unsigned f2tf(float x) {
    unsigned u; asm("cvt.rna.tf32.f32 %0, %1;" : "=r"(u) : "f"(x)); return u;
}
__device__ __forceinline__ float ex2(float x) {
    float y; asm("ex2.approx.f32 %0, %1;" : "=f"(y) : "f"(x)); return y;
}
__device__ __forceinline__ void mma8(float* c, unsigned a0, unsigned a1, unsigned a2, unsigned a3,
                                     unsigned b0, unsigned b1) {
    asm volatile(
        "mma.sync.aligned.m16n8k8.row.col.f32.tf32.tf32.f32 "
        "{%0,%1,%2,%3},{%4,%5,%6,%7},{%8,%9},{%0,%1,%2,%3};\n"
        : "+f"(c[0]), "+f"(c[1]), "+f"(c[2]), "+f"(c[3])
        : "r"(a0), "r"(a1), "r"(a2), "r"(a3), "r"(b0), "r"(b1));
}
__device__ __forceinline__ void cpasync16(void* dst, const void* src) {
    unsigned d = (unsigned)__cvta_generic_to_shared(dst);
    asm volatile("cp.async.cg.shared.global [%0], [%1], 16;\n" :: "r"(d), "l"(src));
}
#define CP_COMMIT() asm volatile("cp.async.commit_group;\n" ::: "memory")
#define CP_WAIT0()  asm volatile("cp.async.wait_group 0;\n" ::: "memory")
#define CP_WAIT1()  asm volatile("cp.async.wait_group 1;\n" ::: "memory")

#define SCQ (0.125f * 1.44269504f)   // 1/sqrt(dh) * log2(e), folded into Q

// ---------------------------------------------------------------------------
// Mask dtype sniffer + expander (bool may arrive as u8 / i32 / f32)
// ---------------------------------------------------------------------------
__global__ void mask_expand_kernel(const unsigned char* __restrict__ raw) {
    __shared__ int s_not_int, s_not_float;
    if (threadIdx.x == 0) { s_not_int = 0; s_not_float = 0; }
    __syncthreads();
    const unsigned int* w = (const unsigned int*)raw;
    for (int i = threadIdx.x; i < 1024; i += blockDim.x) {
        unsigned int x = w[i];
        if (x != 0u && x != 1u)          atomicOr(&s_not_int, 1);
        if (x != 0u && x != 0x3F800000u) atomicOr(&s_not_float, 1);
    }
    __syncthreads();
    int mode = (!s_not_int) ? 0 : ((!s_not_float) ? 1 : 2);
    if (mode == 2) {
        for (int i = threadIdx.x; i < B_ * N_; i += blockDim.x)
            g_mask[i] = raw[i] ? 1 : 0;
    } else {
        for (int i = threadIdx.x; i < B_ * N_; i += blockDim.x)
            g_mask[i] = w[i] ? 1 : 0;
    }
}

// ---------------------------------------------------------------------------
// TF32 GEMM (R4-proven 2-stage): C = A[.,1024] @ B[1024,1024], 128x128 tile,
// BK=16, cp.async double buffer, 256 thr, __launch_bounds__(256,2).
// Epilogue MODE: 0 = plain fp32 store, 1 = tf32-rounded bits,
//                2 = tf32-rounded (acc*SCQ) bits.
// ---------------------------------------------------------------------------
#define GA_STR 20
#define GB_STR 136
#define GA_WORDS (128 * GA_STR)
#define GB_WORDS (16 * GB_STR)

__device__ __forceinline__ void gemm_stage_load(
    const float* __restrict__ A, const float* __restrict__ Bm,
    int rowBase, int colBase, int k0, float* As, float* Bs, int tid)
{
#pragma unroll
    for (int i = 0; i < 2; ++i) {
        int f = tid + i * 256;
        int r = f >> 2, c = (f & 3) * 4;
        cpasync16(As + r * GA_STR + c, A + (size_t)(rowBase + r) * D_ + k0 + c);
    }
#pragma unroll
    for (int i = 0; i < 2; ++i) {
        int f = tid + i * 256;
        int r = f >> 5, c = (f & 31) * 4;
        cpasync16(Bs + r * GB_STR + c, Bm + (size_t)(k0 + r) * D_ + colBase + c);
    }
}

template<int MODE>
__device__ __forceinline__ void gemm_body(
    const float* __restrict__ A, const float* __restrict__ Bm, float* __restrict__ C)
{
    __shared__ float As[2][GA_WORDS];
    __shared__ float Bs[2][GB_WORDS];

    const int tid  = threadIdx.x;
    const int warp = tid >> 5, lane = tid & 31;
    const int g = lane >> 2, t = lane & 3;
    const int wm = (warp >> 2) * 64;
    const int wn = (warp & 3) * 32;
    const int rowBase = blockIdx.y * 128;
    const int colBase = blockIdx.x * 128;

    float acc[4][4][4];
#pragma unroll
    for (int i = 0; i < 4; ++i)
#pragma unroll
        for (int j = 0; j < 4; ++j)
#pragma unroll
            for (int k = 0; k < 4; ++k) acc[i][j][k] = 0.f;

    gemm_stage_load(A, Bm, rowBase, colBase, 0, As[0], Bs[0], tid);
    CP_COMMIT();

    const int NIT = D_ / 16;   // 64
    for (int it = 0; it < NIT; ++it) {
        const int cur = it & 1;
        if (it + 1 < NIT) {
            gemm_stage_load(A, Bm, rowBase, colBase, (it + 1) * 16,
                            As[cur ^ 1], Bs[cur ^ 1], tid);
            CP_COMMIT();
            CP_WAIT1();
        } else {
            CP_WAIT0();
        }
        __syncthreads();

        const float* Ac = As[cur];
        const float* Bc = Bs[cur];
#pragma unroll
        for (int kk = 0; kk < 2; ++kk) {
            const int kb = kk * 8;
            unsigned a[4][4], bf[4][2];
#pragma unroll
            for (int mt = 0; mt < 4; ++mt) {
                int mr = wm + mt * 16;
                a[mt][0] = f2tf(Ac[(mr + g) * GA_STR + kb + t]);
                a[mt][1] = f2tf(Ac[(mr + g + 8) * GA_STR + kb + t]);
                a[mt][2] = f2tf(Ac[(mr + g) * GA_STR + kb + t + 4]);
                a[mt][3] = f2tf(Ac[(mr + g + 8) * GA_STR + kb + t + 4]);
            }
#pragma unroll
            for (int nt = 0; nt < 4; ++nt) {
                int nc = wn + nt * 8 + g;
                bf[nt][0] = f2tf(Bc[(kb + t) * GB_STR + nc]);
                bf[nt][1] = f2tf(Bc[(kb + t + 4) * GB_STR + nc]);
            }
#pragma unroll
            for (int mt = 0; mt < 4; ++mt)
#pragma unroll
                for (int nt = 0; nt < 4; ++nt)
                    mma8(acc[mt][nt], a[mt][0], a[mt][1], a[mt][2], a[mt][3],
                         bf[nt][0], bf[nt][1]);
        }
        __syncthreads();
    }

#pragma unroll
    for (int mt = 0; mt < 4; ++mt) {
        int r0 = rowBase + wm + mt * 16 + g;
#pragma unroll
        for (int nt = 0; nt < 4; ++nt) {
            int c0 = colBase + wn + nt * 8 + 2 * t;
            float v0 = acc[mt][nt][0], v1 = acc[mt][nt][1];
            float v2 = acc[mt][nt][2], v3 = acc[mt][nt][3];
            if (MODE == 2) { v0 *= SCQ; v1 *= SCQ; v2 *= SCQ; v3 *= SCQ; }
            if (MODE != 0) {
                v0 = __uint_as_float(f2tf(v0));
                v1 = __uint_as_float(f2tf(v1));
                v2 = __uint_as_float(f2tf(v2));
                v3 = __uint_as_float(f2tf(v3));
            }
            *(float2*)(C + (size_t)r0 * D_ + c0)       = make_float2(v0, v1);
            *(float2*)(C + (size_t)(r0 + 8) * D_ + c0) = make_float2(v2, v3);
        }
    }
}

__global__ __launch_bounds__(256, 2) void gemm_qkv(
    const float* __restrict__ q, const float* __restrict__ kv,
    const float* __restrict__ WQ, const float* __restrict__ WK,
    const float* __restrict__ WV)
{
    if (blockIdx.z == 0)      gemm_body<2>(q,  WQ, g_Q);
    else if (blockIdx.z == 1) gemm_body<1>(kv, WK, g_K);
    else                      gemm_body<1>(kv, WV, g_V);
}

__global__ __launch_bounds__(256, 2) void gemm_single(
    const float* __restrict__ A, const float* __restrict__ Bm, float* __restrict__ C)
{
    gemm_body<0>(A, Bm, C);
}

// ---------------------------------------------------------------------------
// TF32 flash attention, cp.async double-buffered K/V carrying pre-rounded
// tf32 bits (no conversion anywhere in the loop). Block = 64 query rows,
// 4 warps x 16 rows. Grid: (M/64, NH, B).
// ---------------------------------------------------------------------------
#define AQ_STR 68
#define AK_STR 68
#define AV_STR 72
#define AP_STR 68
#define AQ_OFF 0
#define AK_OFF (64 * AQ_STR)
#define AK_STAGE (64 * AK_STR)
#define AV_OFF (AK_OFF + 2 * AK_STAGE)
#define AV_STAGE (64 * AV_STR)
#define AP_OFF (AV_OFF + 2 * AV_STAGE)
#define AMB_OFF (AP_OFF + 64 * AP_STR)
#define ATT_WORDS (AMB_OFF + 64)          // 26688 words = 106752 B

#define M_INIT (-1.0e4f)
#define MASK_BIAS (-1.0e9f)

__global__ __launch_bounds__(128) void attn_tc(
    const float* __restrict__ Q, const float* __restrict__ K,
    const float* __restrict__ V, float* __restrict__ Cout)
{
    extern __shared__ unsigned smemu[];
    unsigned* Qs = smemu + AQ_OFF;        // tf32 bits (pre-scaled)
    unsigned* Kr = smemu + AK_OFF;        // tf32 bits, 2 stages
    unsigned* Vr = smemu + AV_OFF;        // tf32 bits, 2 stages
    unsigned* Ps = smemu + AP_OFF;        // tf32 bits
    float* mbias = (float*)(smemu + AMB_OFF);

    const int mtile = blockIdx.x, h = blockIdx.y, b = blockIdx.z;
    const int tid = threadIdx.x;
    const int warp = tid >> 5, lane = tid & 31;
    const int g = lane >> 2, t = lane & 3;
    const int mb = warp * 16;
    const int lr = tid >> 1, lch = (tid & 1) * 32;

    const float* Qbase = Q + ((size_t)(b * M_ + mtile * 64)) * D_ + h * DH_;
    const float* Kbase = K + ((size_t)b * N_) * D_ + h * DH_;
    const float* Vbase = V + ((size_t)b * N_) * D_ + h * DH_;

    // Preload group 0: Q tile + K/V tile 0 (all async, all pre-rounded bits)
    {
        const float* qs = Qbase + (size_t)lr * D_ + lch;
        const float* ks = Kbase + (size_t)lr * D_ + lch;
        const float* vs = Vbase + (size_t)lr * D_ + lch;
        unsigned* qd = Qs + lr * AQ_STR + lch;
        unsigned* kd = Kr + lr * AK_STR + lch;
        unsigned* vd = Vr + lr * AV_STR + lch;
#pragma unroll
        for (int i = 0; i < 8; ++i) cpasync16(qd + 4 * i, qs + 4 * i);
#pragma unroll
        for (int i = 0; i < 8; ++i) cpasync16(kd + 4 * i, ks + 4 * i);
#pragma unroll
        for (int i = 0; i < 8; ++i) cpasync16(vd + 4 * i, vs + 4 * i);
    }
    CP_COMMIT();

    float m0 = M_INIT, m1 = M_INIT, l0 = 0.f, l1 = 0.f;
    float o[8][4];
#pragma unroll
    for (int i = 0; i < 8; ++i)
#pragma unroll
        for (int j = 0; j < 4; ++j) o[i][j] = 0.f;

    const int NT = N_ / 64;  // 32
    for (int kt = 0; kt < NT; ++kt) {
        const int cur = kt & 1;
        if (kt + 1 < NT) {
            const int nrow = (kt + 1) * 64 + lr;
            const float* ks = Kbase + (size_t)nrow * D_ + lch;
            const float* vs = Vbase + (size_t)nrow * D_ + lch;
            unsigned* kd = Kr + (cur ^ 1) * AK_STAGE + lr * AK_STR + lch;
            unsigned* vd = Vr + (cur ^ 1) * AV_STAGE + lr * AV_STR + lch;
#pragma unroll
            for (int i = 0; i < 8; ++i) cpasync16(kd + 4 * i, ks + 4 * i);
#pragma unroll
            for (int i = 0; i < 8; ++i) cpasync16(vd + 4 * i, vs + 4 * i);
            CP_COMMIT();
        }
        if (tid < 64)
            mbias[tid] = g_mask[b * N_ + kt * 64 + tid] ? MASK_BIAS : 0.f;
        if (kt + 1 < NT) CP_WAIT1(); else CP_WAIT0();
        __syncthreads();

        const unsigned* Kc = Kr + cur * AK_STAGE;
        const unsigned* Vc = Vr + cur * AV_STAGE;

        // S = Q K^T
        float s[8][4];
#pragma unroll
        for (int i = 0; i < 8; ++i)
#pragma unroll
            for (int j = 0; j < 4; ++j) s[i][j] = 0.f;

#pragma unroll
        for (int kk = 0; kk < 8; ++kk) {
            const int kb = kk * 8;
            unsigned a0 = Qs[(mb + g) * AQ_STR + kb + t];
            unsigned a1 = Qs[(mb + g + 8) * AQ_STR + kb + t];
            unsigned a2 = Qs[(mb + g) * AQ_STR + kb + t + 4];
            unsigned a3 = Qs[(mb + g + 8) * AQ_STR + kb + t + 4];
#pragma unroll
            for (int nt = 0; nt < 8; ++nt) {
                unsigned b0 = Kc[(nt * 8 + g) * AK_STR + kb + t];
                unsigned b1 = Kc[(nt * 8 + g) * AK_STR + kb + t + 4];
                mma8(s[nt], a0, a1, a2, a3, b0, b1);
            }
        }

        // online softmax (base-2)
        float mx0 = -3.0e38f, mx1 = -3.0e38f;
#pragma unroll
        for (int nt = 0; nt < 8; ++nt) {
            float b0 = mbias[nt * 8 + 2 * t];
            float b1 = mbias[nt * 8 + 2 * t + 1];
            s[nt][0] += b0; s[nt][1] += b1;
            s[nt][2] += b0; s[nt][3] += b1;
            mx0 = fmaxf(mx0, fmaxf(s[nt][0], s[nt][1]));
            mx1 = fmaxf(mx1, fmaxf(s[nt][2], s[nt][3]));
        }
        mx0 = fmaxf(mx0, __shfl_xor_sync(0xFFFFFFFFu, mx0, 1));
        mx0 = fmaxf(mx0, __shfl_xor_sync(0xFFFFFFFFu, mx0, 2));
        mx1 = fmaxf(mx1, __shfl_xor_sync(0xFFFFFFFFu, mx1, 1));
        mx1 = fmaxf(mx1, __shfl_xor_sync(0xFFFFFFFFu, mx1, 2));
        float nm0 = fmaxf(m0, mx0), nm1 = fmaxf(m1, mx1);
        float cr0 = ex2(m0 - nm0), cr1 = ex2(m1 - nm1);
        m0 = nm0; m1 = nm1;

        float rs0 = 0.f, rs1 = 0.f;
#pragma unroll
        for (int nt = 0; nt < 8; ++nt) {
            s[nt][0] = ex2(s[nt][0] - nm0);
            s[nt][1] = ex2(s[nt][1] - nm0);
            s[nt][2] = ex2(s[nt][2] - nm1);
            s[nt][3] = ex2(s[nt][3] - nm1);
            rs0 += s[nt][0] + s[nt][1];
            rs1 += s[nt][2] + s[nt][3];
        }
        l0 = l0 * cr0 + rs0;
        l1 = l1 * cr1 + rs1;

#pragma unroll
        for (int nt = 0; nt < 8; ++nt) {
            o[nt][0] *= cr0; o[nt][1] *= cr0;
            o[nt][2] *= cr1; o[nt][3] *= cr1;
            Ps[(mb + g) * AP_STR + nt * 8 + 2 * t]         = f2tf(s[nt][0]);
            Ps[(mb + g) * AP_STR + nt * 8 + 2 * t + 1]     = f2tf(s[nt][1]);
            Ps[(mb + g + 8) * AP_STR + nt * 8 + 2 * t]     = f2tf(s[nt][2]);
            Ps[(mb + g + 8) * AP_STR + nt * 8 + 2 * t + 1] = f2tf(s[nt][3]);
        }
        __syncwarp();

        // O += P V
#pragma unroll
        for (int kk = 0; kk < 8; ++kk) {
            const int kb = kk * 8;
            unsigned a0 = Ps[(mb + g) * AP_STR + kb + t];
            unsigned a1 = Ps[(mb + g + 8) * AP_STR + kb + t];
            unsigned a2 = Ps[(mb + g) * AP_STR + kb + t + 4];
            unsigned a3 = Ps[(mb + g + 8) * AP_STR + kb + t + 4];
#pragma unroll
            for (int nt = 0; nt < 8; ++nt) {
                unsigned b0 = Vc[(kb + t) * AV_STR + nt * 8 + g];
                unsigned b1 = Vc[(kb + t + 4) * AV_STR + nt * 8 + g];
                mma8(o[nt], a0, a1, a2, a3, b0, b1);
            }
        }
        __syncthreads();   // stage fully consumed before reuse
    }

    l0 += __shfl_xor_sync(0xFFFFFFFFu, l0, 1);
    l0 += __shfl_xor_sync(0xFFFFFFFFu, l0, 2);
    l1 += __shfl_xor_sync(0xFFFFFFFFu, l1, 1);
    l1 += __shfl_xor_sync(0xFFFFFFFFu, l1, 2);
    float inv0 = 1.f / l0, inv1 = 1.f / l1;

    const int gr0 = mtile * 64 + mb + g;
    const int gr1 = gr0 + 8;
#pragma unroll
    for (int nt = 0; nt < 8; ++nt) {
        int col = h * DH_ + nt * 8 + 2 * t;
        *(float2*)(Cout + ((size_t)(b * M_ + gr0)) * D_ + col) =
            make_float2(o[nt][0] * inv0, o[nt][1] * inv0);
        *(float2*)(Cout + ((size_t)(b * M_ + gr1)) * D_ + col) =
            make_float2(o[nt][2] * inv1, o[nt][3] * inv1);
    }
}

// ---------------------------------------------------------------------------
// Launch. Inputs: query, key_value, key_padding_mask, W_Q, W_K, W_V, W_O
// ---------------------------------------------------------------------------
extern "C" void kernel_launch(void* const* d_in, const int* in_sizes, int n_in,
                              void* d_out, int out_size)
{
    const float* query = (const float*)d_in[0];
    const float* keyv  = (const float*)d_in[1];
    const unsigned char* mask_raw = (const unsigned char*)d_in[2];
    const float* W_Q = (const float*)d_in[3];
    const float* W_K = (const float*)d_in[4];
    const float* W_V = (const float*)d_in[5];
    const float* W_O = (const float*)d_in[6];
    float* out = (float*)d_out;

    float *gQ, *gK, *gV, *gC;
    cudaGetSymbolAddress((void**)&gQ, g_Q);
    cudaGetSymbolAddress((void**)&gK, g_K);
    cudaGetSymbolAddress((void**)&gV, g_V);
    cudaGetSymbolAddress((void**)&gC, g_C);

    cudaFuncSetAttribute(attn_tc, cudaFuncAttributeMaxDynamicSharedMemorySize,
                         ATT_WORDS * 4);

    mask_expand_kernel<<<1, 1024>>>(mask_raw);

    dim3 gqkv(D_ / 128, (B_ * M_) / 128, 3);
    gemm_qkv<<<gqkv, 256>>>(query, keyv, W_Q, W_K, W_V);

    dim3 gattn(M_ / 64, NH_, B_);
    attn_tc<<<gattn, 128, ATT_WORDS * 4>>>(gQ, gK, gV, gC);

    dim3 gout(D_ / 128, (B_ * M_) / 128);
    gemm_single<<<gout, 256>>>(gC, W_O, out);
}